// round 10
// baseline (speedup 1.0000x reference)
#include <cuda_runtime.h>
#include <stdint.h>
#include <math.h>

// Problem constants (fixed by setup_inputs)
#define B_   4
#define N_   8192
#define M_   8192
#define KNN  16
#define C_   64
#define NBLK1 512
#define MK_INV (1.0f/((float)M_*(float)KNN))
#define FS4  257   // padded feat row stride in float4 (1028 floats)
#define PTS_ 16    // points per k4 block
#define SPAD 20    // s_part row pad (words), 16B-aligned

typedef unsigned long long ull;

// ---------------- packed f32x2 helpers (Blackwell base ISA) ----------------
__device__ __forceinline__ ull fma2(ull a, ull b, ull c) {
    ull d;
    asm("fma.rn.f32x2 %0, %1, %2, %3;" : "=l"(d) : "l"(a), "l"(b), "l"(c));
    return d;
}
__device__ __forceinline__ ull dup2(float x) {
    ull r;
    asm("mov.b64 %0, {%1, %2};" : "=l"(r) : "f"(x), "f"(x));
    return r;
}
__device__ __forceinline__ float2 unpack2(ull v) {
    float2 f;
    asm("mov.b64 {%0, %1}, %2;" : "=f"(f.x), "=f"(f.y) : "l"(v));
    return f;
}

// ---------------- device scratch ----------------
__device__ float  g_xt  [B_*N_*C_];        // x transposed: [B][N][64]
__device__ float  g_post[B_*N_*4];         // pos transposed+padded
__device__ float4 g_pts [B_*M_*KNN];       // normalized pts per neighbor
__device__ float  g_dw  [B_*M_*KNN];       // distance weights
__device__ float  g_t2  [(size_t)B_*M_*256]; // fc2 out, layout [b][m][k][j]
__device__ float  g_part1[B_*NBLK1*16];
__device__ float  g_part2[B_*NBLK1*32];
__device__ float2 g_ab1[B_*16];
__device__ float2 g_ab2[B_*16];
// cv repacked for k4 phase3: [dr][i][oi][og] in float4 units, value = cv row o=og*4+oi,
// d-floats [dr*256 + i*4 .. +3], d = j*64 + c
__device__ __align__(16) float g_cvP[64*1024];

// ---------------- prep kernels ----------------
__global__ void k_xt(const float* __restrict__ x) {
    __shared__ float tile[32][33];
    int b  = blockIdx.z;
    int c0 = blockIdx.y * 32;
    int n0 = blockIdx.x * 32;
    int tx = threadIdx.x, ty = threadIdx.y;   // 32 x 8
    #pragma unroll
    for (int i = 0; i < 32; i += 8)
        tile[ty + i][tx] = x[(size_t)(b*C_ + c0 + ty + i)*N_ + n0 + tx];
    __syncthreads();
    #pragma unroll
    for (int i = 0; i < 32; i += 8)
        g_xt[(size_t)(b*N_ + n0 + ty + i)*C_ + c0 + tx] = tile[tx][ty + i];
}

__global__ void k_pos(const float* __restrict__ pos) {
    int b = blockIdx.y;
    int n = blockIdx.x * 256 + threadIdx.x;
    float4 v;
    v.x = pos[(size_t)(b*3 + 0)*N_ + n];
    v.y = pos[(size_t)(b*3 + 1)*N_ + n];
    v.z = pos[(size_t)(b*3 + 2)*N_ + n];
    v.w = 0.0f;
    ((float4*)g_post)[b*N_ + n] = v;
}

// cv repack for phase3: F = (((dr*64 + i)*4 + oi)*16 + og)*4 + e
__global__ void k_cvp(const float* __restrict__ cv) {
    int F = blockIdx.x * 256 + threadIdx.x;  // 65536
    int e  = F & 3;
    int u2 = F >> 2;
    int og = u2 & 15;
    int oi = (u2 >> 4) & 3;
    int i  = (u2 >> 6) & 63;
    int dr = u2 >> 12;
    int o = og*4 + oi;
    int d = dr*256 + i*4 + e;            // d = j*64 + c
    int c = d & 63, j = d >> 6;
    g_cvP[F] = cv[(size_t)(o*64 + c)*16 + j];
}

// ---------------- pass 1: pts, dw, 9 raw moments ----------------
__global__ void k1(const float* __restrict__ sup, const int* __restrict__ nbr,
                   const float* __restrict__ alpha_p, const float* __restrict__ beta_p,
                   const float* __restrict__ nr_p) {
    __shared__ float s_red[8*9];
    int t = threadIdx.x;
    int b = blockIdx.y;
    int m = blockIdx.x * 16 + (t >> 4);
    int k = t & 15;
    float alpha = alpha_p[0], beta = beta_p[0], inr = 1.0f / nr_p[0];

    int n = nbr[(size_t)(b*M_ + m)*KNN + k];
    float4 p = ((const float4*)g_post)[b*N_ + n];
    float sx = sup[(size_t)(b*3 + 0)*M_ + m];
    float sy = sup[(size_t)(b*3 + 1)*M_ + m];
    float sz = sup[(size_t)(b*3 + 2)*M_ + m];
    float px = p.x - sx, py = p.y - sy, pz = p.z - sz;

    float d  = sqrtf(px*px + py*py + pz*pz);
    float sg = 1.0f / (1.0f + expf(alpha*d - beta));
    float ssum = sg;
    #pragma unroll
    for (int s = 8; s >= 1; s >>= 1) ssum += __shfl_xor_sync(0xffffffffu, ssum, s);
    float dws = ssum + ((ssum == 0.0f) ? 1.0f : 0.0f) + 1e-6f;
    float dwk = sg / dws * (float)KNN;
    g_dw[(size_t)(b*M_ + m)*KNN + k] = dwk;

    px *= inr; py *= inr; pz *= inr;
    g_pts[(size_t)(b*M_ + m)*KNN + k] = make_float4(px, py, pz, 0.0f);

    float mom[9];
    mom[0]=px; mom[1]=py; mom[2]=pz;
    mom[3]=px*px; mom[4]=py*py; mom[5]=pz*pz;
    mom[6]=px*py; mom[7]=px*pz; mom[8]=py*pz;

    int lane = t & 31, wid = t >> 5;
    #pragma unroll
    for (int i = 0; i < 9; i++) {
        float v = mom[i];
        #pragma unroll
        for (int s = 16; s >= 1; s >>= 1) v += __shfl_xor_sync(0xffffffffu, v, s);
        if (lane == 0) s_red[wid*9 + i] = v;
    }
    __syncthreads();
    if (t < 9) {
        float a = 0.0f;
        #pragma unroll
        for (int w = 0; w < 8; w++) a += s_red[w*9 + t];
        g_part1[((size_t)b*NBLK1 + blockIdx.x)*16 + t] = a;
    }
}

// ---------------- stats1: analytic per-channel mean/var from moments ----------------
__global__ void k_stats1(const float* __restrict__ fc1,
                         const float* __restrict__ bnw, const float* __restrict__ bnb) {
    __shared__ float s_w[16];
    __shared__ float s_m[9];
    int b = blockIdx.x, t = threadIdx.x;   // 512 threads
    int lane = t & 31, wid = t >> 5;
    float v[9];
    #pragma unroll
    for (int i = 0; i < 9; i++) v[i] = g_part1[((size_t)b*NBLK1 + t)*16 + i];
    #pragma unroll
    for (int i = 0; i < 9; i++) {
        float r = v[i];
        #pragma unroll
        for (int s = 16; s >= 1; s >>= 1) r += __shfl_xor_sync(0xffffffffu, r, s);
        if (lane == 0) s_w[wid] = r;
        __syncthreads();
        if (t == 0) {
            float a = 0.0f;
            #pragma unroll
            for (int w = 0; w < 16; w++) a += s_w[w];
            s_m[i] = a * MK_INV;
        }
        __syncthreads();
    }
    if (t < 16) {
        float w0 = fc1[t*3], w1 = fc1[t*3+1], w2 = fc1[t*3+2];
        float mean = w0*s_m[0] + w1*s_m[1] + w2*s_m[2];
        float ev2  = w0*w0*s_m[3] + w1*w1*s_m[4] + w2*w2*s_m[5]
                   + 2.0f*(w0*w1*s_m[6] + w0*w2*s_m[7] + w1*w2*s_m[8]);
        float var  = ev2 - mean*mean;
        float rstd = rsqrtf(var + 1e-5f);
        float sc = bnw[t] * rstd;
        g_ab1[b*16 + t] = make_float2(sc, bnb[t] - mean*sc);
    }
}

// ---------------- pass 2: recompute t1, mat1, mp1, t2 = fc2@[mat1;mp1] ----------------
// (stats moved to k_t2stats — no butterfly here)
__global__ void k2(const float* __restrict__ fc1, const float* __restrict__ fc2) {
    __shared__ float s_fc1[64];       // padded [ch][4]
    __shared__ float s_fc2[512];
    __shared__ float2 s_ab[16];
    int t = threadIdx.x, b = blockIdx.y;
    s_fc2[t] = fc2[t];
    s_fc2[t + 256] = fc2[t + 256];
    if (t < 16) {
        s_fc1[t*4+0] = fc1[t*3+0];
        s_fc1[t*4+1] = fc1[t*3+1];
        s_fc1[t*4+2] = fc1[t*3+2];
        s_fc1[t*4+3] = 0.0f;
        s_ab[t] = g_ab1[b*16 + t];
    }
    __syncthreads();

    int m = blockIdx.x * 16 + (t >> 4);
    int k = t & 15;
    float4 p = g_pts[(size_t)(b*M_ + m)*KNN + k];
    float dwk = g_dw[(size_t)(b*M_ + m)*KNN + k];

    float mat1[16], mp1[16];
    const float4* f1 = (const float4*)s_fc1;
    #pragma unroll
    for (int ch = 0; ch < 16; ch++) {
        float4 w = f1[ch];
        float v = w.x*p.x + w.y*p.y + w.z*p.z;
        float2 a = s_ab[ch];
        v = fmaxf(fmaf(v, a.x, a.y), 0.0f);
        mat1[ch] = v;
        float wmax = v * dwk;
        #pragma unroll
        for (int s = 8; s >= 1; s >>= 1) wmax = fmaxf(wmax, __shfl_xor_sync(0xffffffffu, wmax, s));
        mp1[ch] = wmax;
    }

    float t2v[16];
    const float4* f2 = (const float4*)s_fc2;
    #pragma unroll 4
    for (int j = 0; j < 16; j++) {
        float v = 0.0f;
        #pragma unroll
        for (int cq = 0; cq < 4; cq++) {
            float4 w = f2[j*8 + cq];
            v = fmaf(w.x, mat1[cq*4+0], v); v = fmaf(w.y, mat1[cq*4+1], v);
            v = fmaf(w.z, mat1[cq*4+2], v); v = fmaf(w.w, mat1[cq*4+3], v);
        }
        #pragma unroll
        for (int cq = 0; cq < 4; cq++) {
            float4 w = f2[j*8 + 4 + cq];
            v = fmaf(w.x, mp1[cq*4+0], v); v = fmaf(w.y, mp1[cq*4+1], v);
            v = fmaf(w.z, mp1[cq*4+2], v); v = fmaf(w.w, mp1[cq*4+3], v);
        }
        t2v[j] = v;
    }
    float4* o4 = (float4*)(g_t2 + (((size_t)(b*M_ + m)*16) + k)*16);
    o4[0] = make_float4(t2v[0], t2v[1], t2v[2], t2v[3]);
    o4[1] = make_float4(t2v[4], t2v[5], t2v[6], t2v[7]);
    o4[2] = make_float4(t2v[8], t2v[9], t2v[10], t2v[11]);
    o4[3] = make_float4(t2v[12], t2v[13], t2v[14], t2v[15]);
}

// ---------------- t2 stats: coalesced read of g_t2, smem reduction (no shfl) --------
// grid (64, B_), 256 threads; each block covers 128 m-points (2048 (m,k) rows)
__global__ void k_t2stats() {
    __shared__ float s_acc[256][8];
    int b = blockIdx.y, blk = blockIdx.x;
    int t = threadIdx.x;
    int jc = t & 3, r0 = t >> 2;
    const float4* t24 = (const float4*)g_t2;
    size_t base = ((size_t)(b*M_) + blk*128) * 16;   // row units of 16 floats
    float4 s = make_float4(0,0,0,0), q = make_float4(0,0,0,0);
    #pragma unroll 4
    for (int it = 0; it < 32; it++) {
        int r = it*64 + r0;          // 0..2047
        float4 v = t24[(base + r)*4 + jc];
        s.x += v.x; s.y += v.y; s.z += v.z; s.w += v.w;
        q.x = fmaf(v.x, v.x, q.x); q.y = fmaf(v.y, v.y, q.y);
        q.z = fmaf(v.z, v.z, q.z); q.w = fmaf(v.w, v.w, q.w);
    }
    s_acc[t][0]=s.x; s_acc[t][1]=s.y; s_acc[t][2]=s.z; s_acc[t][3]=s.w;
    s_acc[t][4]=q.x; s_acc[t][5]=q.y; s_acc[t][6]=q.z; s_acc[t][7]=q.w;
    __syncthreads();
    if (t < 32) {
        int jj = t >> 2, jc2 = t & 3;
        float a = 0.0f;
        #pragma unroll 8
        for (int r = 0; r < 64; r++) a += s_acc[r*4 + jc2][jj];
        int j = jc2*4 + (jj & 3);
        int idx = (jj < 4) ? j : (16 + j);
        g_part2[((size_t)(b*64) + blk)*32 + idx] = a;
    }
}

// ---------------- stats2 finalize: 64 partials -> ab2 ----------------
__global__ void k_stats2b(const float* __restrict__ bnw, const float* __restrict__ bnb) {
    __shared__ float s_c[32];
    int b = blockIdx.x, t = threadIdx.x;   // 32 threads
    float a = 0.0f;
    #pragma unroll 8
    for (int r = 0; r < 64; r++) a += g_part2[((size_t)(b*64) + r)*32 + t];
    s_c[t] = a;
    __syncwarp();
    if (t < 16) {
        float mean = s_c[t] * MK_INV;
        float var  = s_c[t+16] * MK_INV - mean*mean;
        float rstd = rsqrtf(var + 1e-5f);
        float sc = bnw[t] * rstd;
        g_ab2[b*16 + t] = make_float2(sc, bnb[t] - mean*sc);
    }
}

// ---------------- pass 3 (fused): mat3, gather+feat GEMM, shuffle-free cv GEMM ------
// 256 threads, 16 points per block, 2 CTAs/SM.
// smem floats: s_feat 16448 | s_part 5120 (also mat3 4096) | s_fc3 512 | s_ab 32 | s_idx 256
#define OFP_PART 16448
#define OFP_FC3  (16448 + 5120)
#define OFP_AB   (16448 + 5120 + 512)
#define OFP_IDX  (16448 + 5120 + 512 + 32)
#define K4_SMEM  ((16448 + 5120 + 512 + 32 + 256) * 4)

__global__ void __launch_bounds__(256, 2)
k4(const int* __restrict__ nbr, const float* __restrict__ fc3, float* __restrict__ out) {
    extern __shared__ __align__(16) float sm[];
    float* s_feat = sm;                      // 16 rows x 1028 floats
    float* s_mat3 = sm + OFP_PART;           // phase1 mat3 (4096f) / phase3 s_part (5120f)
    float* s_fc3  = sm + OFP_FC3;
    float* s_ab   = sm + OFP_AB;
    int*   s_idx  = (int*)(sm + OFP_IDX);

    int t = threadIdx.x, b = blockIdx.y;
    int m0 = blockIdx.x * PTS_;

    s_fc3[t] = fc3[t];
    s_fc3[t + 256] = fc3[t + 256];
    s_idx[t] = nbr[((size_t)(b*M_) + m0)*KNN + t];
    if (t < 16) { float2 a = g_ab2[b*16 + t]; s_ab[t] = a.x; s_ab[16 + t] = a.y; }
    __syncthreads();

    // ---- phase 1: mat3[pt][k][j] ----
    {
        int pt = t >> 4, k = t & 15;
        int m = m0 + pt;
        float dwk = g_dw[(size_t)(b*M_ + m)*KNN + k];
        const float4* t24 = (const float4*)(g_t2 + (((size_t)(b*M_ + m)*16) + k)*16);
        float4 q0 = t24[0], q1 = t24[1], q2 = t24[2], q3 = t24[3];
        float mat2[16], mp2[16];
        mat2[0]=q0.x; mat2[1]=q0.y; mat2[2]=q0.z; mat2[3]=q0.w;
        mat2[4]=q1.x; mat2[5]=q1.y; mat2[6]=q1.z; mat2[7]=q1.w;
        mat2[8]=q2.x; mat2[9]=q2.y; mat2[10]=q2.z; mat2[11]=q2.w;
        mat2[12]=q3.x; mat2[13]=q3.y; mat2[14]=q3.z; mat2[15]=q3.w;
        #pragma unroll
        for (int ch = 0; ch < 16; ch++) {
            float v = fmaxf(fmaf(mat2[ch], s_ab[ch], s_ab[16 + ch]), 0.0f);
            mat2[ch] = v;
            float w = v * dwk;
            #pragma unroll
            for (int s = 8; s >= 1; s >>= 1) w = fmaxf(w, __shfl_xor_sync(0xffffffffu, w, s));
            mp2[ch] = w;
        }
        const float4* f3 = (const float4*)s_fc3;
        float t3[16];
        #pragma unroll 4
        for (int j = 0; j < 16; j++) {
            float v = 0.0f;
            #pragma unroll
            for (int cq = 0; cq < 4; cq++) {
                float4 w = f3[j*8 + cq];
                v = fmaf(w.x, mat2[cq*4+0], v); v = fmaf(w.y, mat2[cq*4+1], v);
                v = fmaf(w.z, mat2[cq*4+2], v); v = fmaf(w.w, mat2[cq*4+3], v);
            }
            #pragma unroll
            for (int cq = 0; cq < 4; cq++) {
                float4 w = f3[j*8 + 4 + cq];
                v = fmaf(w.x, mp2[cq*4+0], v); v = fmaf(w.y, mp2[cq*4+1], v);
                v = fmaf(w.z, mp2[cq*4+2], v); v = fmaf(w.w, mp2[cq*4+3], v);
            }
            t3[j] = fmaxf(v, 0.0f) * dwk;
        }
        float4* sm4 = (float4*)s_mat3;
        #pragma unroll
        for (int jg = 0; jg < 4; jg++)
            sm4[pt*64 + k*4 + jg] = make_float4(t3[jg*4], t3[jg*4+1], t3[jg*4+2], t3[jg*4+3]);
    }
    __syncthreads();

    // ---- phase 2: feat[pt][d = j*64 + c], packed f32x2 ----
    {
        int pt = t >> 4, cg = t & 15;           // 4 channels per thread
        ull facc2[4][8];
        #pragma unroll
        for (int i = 0; i < 4; i++)
            #pragma unroll
            for (int jp = 0; jp < 8; jp++) facc2[i][jp] = 0ull;

        const float4* xt4 = (const float4*)g_xt;
        const ulonglong2* sm2 = (const ulonglong2*)s_mat3;
        #pragma unroll 2
        for (int k = 0; k < 16; k++) {
            int n = s_idx[pt*16 + k];
            float4 xv = xt4[(size_t)(b*N_ + n)*16 + cg];
            ull d0 = dup2(xv.x), d1 = dup2(xv.y), d2 = dup2(xv.z), d3 = dup2(xv.w);
            #pragma unroll
            for (int q = 0; q < 4; q++) {
                ulonglong2 mv = sm2[pt*64 + k*4 + q];
                facc2[0][2*q]   = fma2(d0, mv.x, facc2[0][2*q]);
                facc2[1][2*q]   = fma2(d1, mv.x, facc2[1][2*q]);
                facc2[2][2*q]   = fma2(d2, mv.x, facc2[2][2*q]);
                facc2[3][2*q]   = fma2(d3, mv.x, facc2[3][2*q]);
                facc2[0][2*q+1] = fma2(d0, mv.y, facc2[0][2*q+1]);
                facc2[1][2*q+1] = fma2(d1, mv.y, facc2[1][2*q+1]);
                facc2[2][2*q+1] = fma2(d2, mv.y, facc2[2][2*q+1]);
                facc2[3][2*q+1] = fma2(d3, mv.y, facc2[3][2*q+1]);
            }
        }
        float4* sf4 = (float4*)s_feat;
        #pragma unroll
        for (int jp = 0; jp < 8; jp++) {
            float2 a0 = unpack2(facc2[0][jp]);
            float2 a1 = unpack2(facc2[1][jp]);
            float2 a2 = unpack2(facc2[2][jp]);
            float2 a3 = unpack2(facc2[3][jp]);
            sf4[pt*FS4 + (2*jp)  *16 + cg] = make_float4(a0.x, a1.x, a2.x, a3.x);
            sf4[pt*FS4 + (2*jp+1)*16 + cg] = make_float4(a0.y, a1.y, a2.y, a3.y);
        }
    }
    __syncthreads();

    // ---- phase 3: shuffle-free cv GEMM with d-range split ----
    // thread: dr = t>>6 (d-range of 256 floats), og = (t&63)>>2, pg = t&3
    // computes 4o x 4p partial over its 256-float d-range
    {
        int dr = t >> 6;
        int tid = t & 63;
        int og = tid >> 2, pg = tid & 3;
        const ulonglong2* cv2 = (const ulonglong2*)g_cvP;   // [dr][i][oi][og]
        const ulonglong2* sf2 = (const ulonglong2*)s_feat;
        const ulonglong2* cvp = cv2 + ((size_t)dr*64*4)*16 + og;  // + i*64 + oi*16
        const ulonglong2* fp  = sf2 + (size_t)pg*4*FS4 + dr*64;   // + pi*FS4 + i

        ull acc[4][4];
        #pragma unroll
        for (int oi = 0; oi < 4; oi++)
            #pragma unroll
            for (int pi = 0; pi < 4; pi++) acc[oi][pi] = 0ull;

        #pragma unroll 2
        for (int i = 0; i < 64; i++) {
            ulonglong2 w0 = cvp[i*64 +  0];
            ulonglong2 w1 = cvp[i*64 + 16];
            ulonglong2 w2 = cvp[i*64 + 32];
            ulonglong2 w3 = cvp[i*64 + 48];
            #pragma unroll
            for (int pi = 0; pi < 4; pi++) {
                ulonglong2 fv = fp[pi*FS4 + i];
                acc[0][pi] = fma2(w0.x, fv.x, acc[0][pi]);
                acc[0][pi] = fma2(w0.y, fv.y, acc[0][pi]);
                acc[1][pi] = fma2(w1.x, fv.x, acc[1][pi]);
                acc[1][pi] = fma2(w1.y, fv.y, acc[1][pi]);
                acc[2][pi] = fma2(w2.x, fv.x, acc[2][pi]);
                acc[2][pi] = fma2(w2.y, fv.y, acc[2][pi]);
                acc[3][pi] = fma2(w3.x, fv.x, acc[3][pi]);
                acc[3][pi] = fma2(w3.y, fv.y, acc[3][pi]);
            }
        }
        // stage partials: s_part[dr][o][SPAD] rows, float4 over pi
        float* s_part = s_mat3;
        #pragma unroll
        for (int oi = 0; oi < 4; oi++) {
            int o = og*4 + oi;
            float2 h0 = unpack2(acc[oi][0]);
            float2 h1 = unpack2(acc[oi][1]);
            float2 h2 = unpack2(acc[oi][2]);
            float2 h3 = unpack2(acc[oi][3]);
            float4 v = make_float4(h0.x + h0.y, h1.x + h1.y, h2.x + h2.y, h3.x + h3.y);
            *(float4*)(s_part + (dr*64 + o)*SPAD + pg*4) = v;
        }
    }
    __syncthreads();

    // ---- final: sum 4 d-range partials, coalesced store ----
    {
        int o = t >> 2, pq = t & 3;
        const float* s_part = s_mat3;
        float4 v0 = *(const float4*)(s_part + (0*64 + o)*SPAD + pq*4);
        float4 v1 = *(const float4*)(s_part + (1*64 + o)*SPAD + pq*4);
        float4 v2 = *(const float4*)(s_part + (2*64 + o)*SPAD + pq*4);
        float4 v3 = *(const float4*)(s_part + (3*64 + o)*SPAD + pq*4);
        float4 v = make_float4(v0.x+v1.x+v2.x+v3.x, v0.y+v1.y+v2.y+v3.y,
                               v0.z+v1.z+v2.z+v3.z, v0.w+v1.w+v2.w+v3.w);
        ((float4*)out)[((size_t)(b*64 + o))*2048 + (m0 >> 2) + pq] = v;
    }
}

// ---------------- launch ----------------
extern "C" void kernel_launch(void* const* d_in, const int* in_sizes, int n_in,
                              void* d_out, int out_size) {
    const float* x     = (const float*)d_in[0];
    const float* pos   = (const float*)d_in[1];
    const float* sup   = (const float*)d_in[2];
    const int*   nbr   = (const int*)  d_in[3];
    const float* alpha = (const float*)d_in[4];
    const float* beta  = (const float*)d_in[5];
    const float* nr    = (const float*)d_in[6];
    const float* fc1   = (const float*)d_in[7];
    const float* fc2   = (const float*)d_in[8];
    const float* fc3   = (const float*)d_in[9];
    const float* bn1w  = (const float*)d_in[10];
    const float* bn1b  = (const float*)d_in[11];
    const float* bn2w  = (const float*)d_in[12];
    const float* bn2b  = (const float*)d_in[13];
    const float* cvw   = (const float*)d_in[14];
    float* out = (float*)d_out;

    cudaFuncSetAttribute((const void*)k4, cudaFuncAttributeMaxDynamicSharedMemorySize, K4_SMEM);

    k_xt     <<<dim3(N_/32, C_/32, B_), dim3(32, 8)>>>(x);
    k_pos    <<<dim3(N_/256, B_), 256>>>(pos);
    k_cvp    <<<256, 256>>>(cvw);
    k1       <<<dim3(NBLK1, B_), 256>>>(sup, nbr, alpha, beta, nr);
    k_stats1 <<<B_, 512>>>(fc1, bn1w, bn1b);
    k2       <<<dim3(NBLK1, B_), 256>>>(fc1, fc2);
    k_t2stats<<<dim3(64, B_), 256>>>();
    k_stats2b<<<B_, 32>>>(bn2w, bn2b);
    k4       <<<dim3(M_/PTS_, B_), 256, K4_SMEM>>>(nbr, fc3, out);
}

// round 11
// speedup vs baseline: 1.2087x; 1.2087x over previous
#include <cuda_runtime.h>
#include <stdint.h>
#include <math.h>

// Problem constants (fixed by setup_inputs)
#define B_   4
#define N_   8192
#define M_   8192
#define KNN  16
#define C_   64
#define NBLK1 512
#define MK_INV (1.0f/((float)M_*(float)KNN))
#define FS4  257   // padded feat row stride in float4 (1028 floats)
#define PTS_ 16    // points per k4 block

typedef unsigned long long ull;

// ---------------- packed f32x2 helpers (Blackwell base ISA) ----------------
__device__ __forceinline__ ull fma2(ull a, ull b, ull c) {
    ull d;
    asm("fma.rn.f32x2 %0, %1, %2, %3;" : "=l"(d) : "l"(a), "l"(b), "l"(c));
    return d;
}
__device__ __forceinline__ ull dup2(float x) {
    ull r;
    asm("mov.b64 %0, {%1, %2};" : "=l"(r) : "f"(x), "f"(x));
    return r;
}
__device__ __forceinline__ float2 unpack2(ull v) {
    float2 f;
    asm("mov.b64 {%0, %1}, %2;" : "=f"(f.x), "=f"(f.y) : "l"(v));
    return f;
}

// Partition-reduce 32 values across 32 lanes: 31 shfl total.
// On return, lane l holds the full sum of value index l.
__device__ __forceinline__ float preduce32(float* v, int lane) {
    #pragma unroll
    for (int m = 16; m >= 1; m >>= 1) {
        bool b = (lane & m) != 0;
        #pragma unroll
        for (int i = 0; i < m; i++) {
            float send = b ? v[i] : v[i + m];
            float r = __shfl_xor_sync(0xffffffffu, send, m);
            v[i] = (b ? v[i + m] : v[i]) + r;
        }
    }
    return v[0];
}

// ---------------- device scratch ----------------
__device__ float  g_xt  [B_*N_*C_];        // x transposed: [B][N][64]
__device__ float  g_post[B_*N_*4];         // pos transposed+padded
__device__ float4 g_pts [B_*M_*KNN];       // normalized pts per neighbor
__device__ float  g_dw  [B_*M_*KNN];       // distance weights
__device__ float  g_t2  [(size_t)B_*M_*256]; // fc2 out, layout [b][m][k][j]
__device__ float  g_part1[B_*NBLK1*16];
__device__ float  g_part2[B_*NBLK1*32];
__device__ float2 g_ab1[B_*16];
__device__ float2 g_ab2[B_*16];
__device__ __align__(16) float g_cvP[64*1024];  // cv repacked [o][d], d=j*64+c

// ---------------- prep kernels ----------------
__global__ void k_xt(const float* __restrict__ x) {
    __shared__ float tile[32][33];
    int b  = blockIdx.z;
    int c0 = blockIdx.y * 32;
    int n0 = blockIdx.x * 32;
    int tx = threadIdx.x, ty = threadIdx.y;   // 32 x 8
    #pragma unroll
    for (int i = 0; i < 32; i += 8)
        tile[ty + i][tx] = x[(size_t)(b*C_ + c0 + ty + i)*N_ + n0 + tx];
    __syncthreads();
    #pragma unroll
    for (int i = 0; i < 32; i += 8)
        g_xt[(size_t)(b*N_ + n0 + ty + i)*C_ + c0 + tx] = tile[tx][ty + i];
}

__global__ void k_pos(const float* __restrict__ pos) {
    int b = blockIdx.y;
    int n = blockIdx.x * 256 + threadIdx.x;
    float4 v;
    v.x = pos[(size_t)(b*3 + 0)*N_ + n];
    v.y = pos[(size_t)(b*3 + 1)*N_ + n];
    v.z = pos[(size_t)(b*3 + 2)*N_ + n];
    v.w = 0.0f;
    ((float4*)g_post)[b*N_ + n] = v;
}

// cv2[o][d] with d = j*64 + c
__global__ void k_cvp(const float* __restrict__ cv) {
    int g = blockIdx.x * 256 + threadIdx.x;  // 65536
    int o = g >> 10;
    int d = g & 1023;
    int c = d & 63;
    int j = d >> 6;
    g_cvP[g] = cv[(size_t)(o*64 + c)*16 + j];
}

// ---------------- pass 1: pts, dw, 9 raw moments ----------------
__global__ void k1(const float* __restrict__ sup, const int* __restrict__ nbr,
                   const float* __restrict__ alpha_p, const float* __restrict__ beta_p,
                   const float* __restrict__ nr_p) {
    __shared__ float s_red[8*9];
    int t = threadIdx.x;
    int b = blockIdx.y;
    int m = blockIdx.x * 16 + (t >> 4);
    int k = t & 15;
    float alpha = alpha_p[0], beta = beta_p[0], inr = 1.0f / nr_p[0];

    int n = nbr[(size_t)(b*M_ + m)*KNN + k];
    float4 p = ((const float4*)g_post)[b*N_ + n];
    float sx = sup[(size_t)(b*3 + 0)*M_ + m];
    float sy = sup[(size_t)(b*3 + 1)*M_ + m];
    float sz = sup[(size_t)(b*3 + 2)*M_ + m];
    float px = p.x - sx, py = p.y - sy, pz = p.z - sz;

    float d  = sqrtf(px*px + py*py + pz*pz);
    float sg = 1.0f / (1.0f + expf(alpha*d - beta));
    float ssum = sg;
    #pragma unroll
    for (int s = 8; s >= 1; s >>= 1) ssum += __shfl_xor_sync(0xffffffffu, ssum, s);
    float dws = ssum + ((ssum == 0.0f) ? 1.0f : 0.0f) + 1e-6f;
    float dwk = sg / dws * (float)KNN;
    g_dw[(size_t)(b*M_ + m)*KNN + k] = dwk;

    px *= inr; py *= inr; pz *= inr;
    g_pts[(size_t)(b*M_ + m)*KNN + k] = make_float4(px, py, pz, 0.0f);

    float mom[9];
    mom[0]=px; mom[1]=py; mom[2]=pz;
    mom[3]=px*px; mom[4]=py*py; mom[5]=pz*pz;
    mom[6]=px*py; mom[7]=px*pz; mom[8]=py*pz;

    int lane = t & 31, wid = t >> 5;
    #pragma unroll
    for (int i = 0; i < 9; i++) {
        float v = mom[i];
        #pragma unroll
        for (int s = 16; s >= 1; s >>= 1) v += __shfl_xor_sync(0xffffffffu, v, s);
        if (lane == 0) s_red[wid*9 + i] = v;
    }
    __syncthreads();
    if (t < 9) {
        float a = 0.0f;
        #pragma unroll
        for (int w = 0; w < 8; w++) a += s_red[w*9 + t];
        g_part1[((size_t)b*NBLK1 + blockIdx.x)*16 + t] = a;
    }
}

// ---------------- stats1: analytic per-channel mean/var from moments ----------------
__global__ void k_stats1(const float* __restrict__ fc1,
                         const float* __restrict__ bnw, const float* __restrict__ bnb) {
    __shared__ float s_w[16];
    __shared__ float s_m[9];
    int b = blockIdx.x, t = threadIdx.x;   // 512 threads
    int lane = t & 31, wid = t >> 5;
    float v[9];
    #pragma unroll
    for (int i = 0; i < 9; i++) v[i] = g_part1[((size_t)b*NBLK1 + t)*16 + i];
    #pragma unroll
    for (int i = 0; i < 9; i++) {
        float r = v[i];
        #pragma unroll
        for (int s = 16; s >= 1; s >>= 1) r += __shfl_xor_sync(0xffffffffu, r, s);
        if (lane == 0) s_w[wid] = r;
        __syncthreads();
        if (t == 0) {
            float a = 0.0f;
            #pragma unroll
            for (int w = 0; w < 16; w++) a += s_w[w];
            s_m[i] = a * MK_INV;
        }
        __syncthreads();
    }
    if (t < 16) {
        float w0 = fc1[t*3], w1 = fc1[t*3+1], w2 = fc1[t*3+2];
        float mean = w0*s_m[0] + w1*s_m[1] + w2*s_m[2];
        float ev2  = w0*w0*s_m[3] + w1*w1*s_m[4] + w2*w2*s_m[5]
                   + 2.0f*(w0*w1*s_m[6] + w0*w2*s_m[7] + w1*w2*s_m[8]);
        float var  = ev2 - mean*mean;
        float rstd = rsqrtf(var + 1e-5f);
        float sc = bnw[t] * rstd;
        g_ab1[b*16 + t] = make_float2(sc, bnb[t] - mean*sc);
    }
}

// ---------------- pass 2: recompute t1, mat1, mp1, t2 = fc2@[mat1;mp1], stats ----------------
__global__ void k2(const float* __restrict__ fc1, const float* __restrict__ fc2) {
    __shared__ float s_fc1[64];       // padded [ch][4]
    __shared__ float s_fc2[512];
    __shared__ float2 s_ab[16];
    __shared__ float s_red[8*32];
    int t = threadIdx.x, b = blockIdx.y;
    s_fc2[t] = fc2[t];
    s_fc2[t + 256] = fc2[t + 256];
    if (t < 16) {
        s_fc1[t*4+0] = fc1[t*3+0];
        s_fc1[t*4+1] = fc1[t*3+1];
        s_fc1[t*4+2] = fc1[t*3+2];
        s_fc1[t*4+3] = 0.0f;
        s_ab[t] = g_ab1[b*16 + t];
    }
    __syncthreads();

    int m = blockIdx.x * 16 + (t >> 4);
    int k = t & 15;
    float4 p = g_pts[(size_t)(b*M_ + m)*KNN + k];
    float dwk = g_dw[(size_t)(b*M_ + m)*KNN + k];

    float mat1[16], mp1[16];
    const float4* f1 = (const float4*)s_fc1;
    #pragma unroll
    for (int ch = 0; ch < 16; ch++) {
        float4 w = f1[ch];
        float v = w.x*p.x + w.y*p.y + w.z*p.z;
        float2 a = s_ab[ch];
        v = fmaxf(fmaf(v, a.x, a.y), 0.0f);
        mat1[ch] = v;
        float wmax = v * dwk;
        #pragma unroll
        for (int s = 8; s >= 1; s >>= 1) wmax = fmaxf(wmax, __shfl_xor_sync(0xffffffffu, wmax, s));
        mp1[ch] = wmax;
    }

    float t2v[16];
    const float4* f2 = (const float4*)s_fc2;
    #pragma unroll 4
    for (int j = 0; j < 16; j++) {
        float v = 0.0f;
        #pragma unroll
        for (int cq = 0; cq < 4; cq++) {
            float4 w = f2[j*8 + cq];
            v = fmaf(w.x, mat1[cq*4+0], v); v = fmaf(w.y, mat1[cq*4+1], v);
            v = fmaf(w.z, mat1[cq*4+2], v); v = fmaf(w.w, mat1[cq*4+3], v);
        }
        #pragma unroll
        for (int cq = 0; cq < 4; cq++) {
            float4 w = f2[j*8 + 4 + cq];
            v = fmaf(w.x, mp1[cq*4+0], v); v = fmaf(w.y, mp1[cq*4+1], v);
            v = fmaf(w.z, mp1[cq*4+2], v); v = fmaf(w.w, mp1[cq*4+3], v);
        }
        t2v[j] = v;
    }
    // store t2 layout [b][m][k][j]: 4 contiguous float4 per thread
    float4* o4 = (float4*)(g_t2 + (((size_t)(b*M_ + m)*16) + k)*16);
    o4[0] = make_float4(t2v[0], t2v[1], t2v[2], t2v[3]);
    o4[1] = make_float4(t2v[4], t2v[5], t2v[6], t2v[7]);
    o4[2] = make_float4(t2v[8], t2v[9], t2v[10], t2v[11]);
    o4[3] = make_float4(t2v[12], t2v[13], t2v[14], t2v[15]);

    // stats via partition-reduce: 31 shfl instead of 160
    float stat[32];
    #pragma unroll
    for (int j = 0; j < 16; j++) { stat[j] = t2v[j]; stat[16+j] = t2v[j]*t2v[j]; }
    int lane = t & 31, wid = t >> 5;
    float r = preduce32(stat, lane);
    s_red[wid*32 + lane] = r;
    __syncthreads();
    if (t < 32) {
        float a = 0.0f;
        #pragma unroll
        for (int w = 0; w < 8; w++) a += s_red[w*32 + t];
        g_part2[((size_t)b*NBLK1 + blockIdx.x)*32 + t] = a;
    }
}

// ---------------- stats2: parallel reduction of 32 stats ----------------
__global__ void k_stats2(const float* __restrict__ bnw, const float* __restrict__ bnb) {
    __shared__ float s_p[32*32];
    __shared__ float s_c[32];
    int b = blockIdx.x, t = threadIdx.x;   // 1024 threads
    int w = t >> 5, s = t & 31;
    float a = 0.0f;
    #pragma unroll
    for (int i = 0; i < 16; i++)
        a += g_part2[((size_t)b*NBLK1 + w*16 + i)*32 + s];
    s_p[w*32 + s] = a;
    __syncthreads();
    if (t < 32) {
        float r = 0.0f;
        #pragma unroll
        for (int w2 = 0; w2 < 32; w2++) r += s_p[w2*32 + t];
        s_c[t] = r;
    }
    __syncthreads();
    if (t < 16) {
        float mean = s_c[t] * MK_INV;
        float var  = s_c[t+16] * MK_INV - mean*mean;
        float rstd = rsqrtf(var + 1e-5f);
        float sc = bnw[t] * rstd;
        g_ab2[b*16 + t] = make_float2(sc, bnb[t] - mean*sc);
    }
}

// ---------------- pass 3 (fused): mat3, gather+feat GEMM, cv GEMM ----------------
// 256 threads, 16 points per block, 2 CTAs/SM.
// smem floats: s_feat 16448 | s_mat3 4096 | s_fc3 512 | s_ab 32 | s_idx 256i
#define K4_SMEM ((16448 + 4096 + 512 + 32 + 256) * 4)

__global__ void __launch_bounds__(256, 2)
k4(const int* __restrict__ nbr, const float* __restrict__ fc3, float* __restrict__ out) {
    extern __shared__ __align__(16) float sm[];
    float* s_feat = sm;                          // 16448 floats (16 rows x 1028)
    float* s_mat3 = sm + 16448;                  // 4096 (also reused as s_fin)
    float* s_fc3  = sm + 16448 + 4096;           // 512
    float* s_ab   = sm + 16448 + 4096 + 512;     // 32
    int*   s_idx  = (int*)(sm + 16448 + 4096 + 512 + 32); // 256

    int t = threadIdx.x, b = blockIdx.y;
    int m0 = blockIdx.x * PTS_;

    s_fc3[t] = fc3[t];
    s_fc3[t + 256] = fc3[t + 256];
    s_idx[t] = nbr[((size_t)(b*M_) + m0)*KNN + t];
    if (t < 16) { float2 a = g_ab2[b*16 + t]; s_ab[t] = a.x; s_ab[16 + t] = a.y; }
    __syncthreads();

    // ---- phase 1: mat3[pt][k][j] ----
    {
        int pt = t >> 4, k = t & 15;
        int m = m0 + pt;
        float dwk = g_dw[(size_t)(b*M_ + m)*KNN + k];
        const float4* t24 = (const float4*)(g_t2 + (((size_t)(b*M_ + m)*16) + k)*16);
        float4 q0 = t24[0], q1 = t24[1], q2 = t24[2], q3 = t24[3];
        float mat2[16], mp2[16];
        mat2[0]=q0.x; mat2[1]=q0.y; mat2[2]=q0.z; mat2[3]=q0.w;
        mat2[4]=q1.x; mat2[5]=q1.y; mat2[6]=q1.z; mat2[7]=q1.w;
        mat2[8]=q2.x; mat2[9]=q2.y; mat2[10]=q2.z; mat2[11]=q2.w;
        mat2[12]=q3.x; mat2[13]=q3.y; mat2[14]=q3.z; mat2[15]=q3.w;
        #pragma unroll
        for (int ch = 0; ch < 16; ch++) {
            float v = fmaxf(fmaf(mat2[ch], s_ab[ch], s_ab[16 + ch]), 0.0f);
            mat2[ch] = v;
            float w = v * dwk;
            #pragma unroll
            for (int s = 8; s >= 1; s >>= 1) w = fmaxf(w, __shfl_xor_sync(0xffffffffu, w, s));
            mp2[ch] = w;
        }
        const float4* f3 = (const float4*)s_fc3;
        float t3[16];
        #pragma unroll 4
        for (int j = 0; j < 16; j++) {
            float v = 0.0f;
            #pragma unroll
            for (int cq = 0; cq < 4; cq++) {
                float4 w = f3[j*8 + cq];
                v = fmaf(w.x, mat2[cq*4+0], v); v = fmaf(w.y, mat2[cq*4+1], v);
                v = fmaf(w.z, mat2[cq*4+2], v); v = fmaf(w.w, mat2[cq*4+3], v);
            }
            #pragma unroll
            for (int cq = 0; cq < 4; cq++) {
                float4 w = f3[j*8 + 4 + cq];
                v = fmaf(w.x, mp2[cq*4+0], v); v = fmaf(w.y, mp2[cq*4+1], v);
                v = fmaf(w.z, mp2[cq*4+2], v); v = fmaf(w.w, mp2[cq*4+3], v);
            }
            t3[j] = fmaxf(v, 0.0f) * dwk;
        }
        float4* sm4 = (float4*)s_mat3;
        #pragma unroll
        for (int jg = 0; jg < 4; jg++)
            sm4[pt*64 + k*4 + jg] = make_float4(t3[jg*4], t3[jg*4+1], t3[jg*4+2], t3[jg*4+3]);
    }
    __syncthreads();

    // ---- phase 2: feat[pt][d = j*64 + c], packed f32x2 ----
    {
        int pt = t >> 4, cg = t & 15;           // 4 channels per thread
        ull facc2[4][8];
        #pragma unroll
        for (int i = 0; i < 4; i++)
            #pragma unroll
            for (int jp = 0; jp < 8; jp++) facc2[i][jp] = 0ull;

        const float4* xt4 = (const float4*)g_xt;
        const ulonglong2* sm2 = (const ulonglong2*)s_mat3;
        #pragma unroll 2
        for (int k = 0; k < 16; k++) {
            int n = s_idx[pt*16 + k];
            float4 xv = xt4[(size_t)(b*N_ + n)*16 + cg];
            ull d0 = dup2(xv.x), d1 = dup2(xv.y), d2 = dup2(xv.z), d3 = dup2(xv.w);
            #pragma unroll
            for (int q = 0; q < 4; q++) {
                ulonglong2 mv = sm2[pt*64 + k*4 + q];
                facc2[0][2*q]   = fma2(d0, mv.x, facc2[0][2*q]);
                facc2[1][2*q]   = fma2(d1, mv.x, facc2[1][2*q]);
                facc2[2][2*q]   = fma2(d2, mv.x, facc2[2][2*q]);
                facc2[3][2*q]   = fma2(d3, mv.x, facc2[3][2*q]);
                facc2[0][2*q+1] = fma2(d0, mv.y, facc2[0][2*q+1]);
                facc2[1][2*q+1] = fma2(d1, mv.y, facc2[1][2*q+1]);
                facc2[2][2*q+1] = fma2(d2, mv.y, facc2[2][2*q+1]);
                facc2[3][2*q+1] = fma2(d3, mv.y, facc2[3][2*q+1]);
            }
        }
        float4* sf4 = (float4*)s_feat;
        #pragma unroll
        for (int jp = 0; jp < 8; jp++) {
            float2 a0 = unpack2(facc2[0][jp]);
            float2 a1 = unpack2(facc2[1][jp]);
            float2 a2 = unpack2(facc2[2][jp]);
            float2 a3 = unpack2(facc2[3][jp]);
            sf4[pt*FS4 + (2*jp)  *16 + cg] = make_float4(a0.x, a1.x, a2.x, a3.x);
            sf4[pt*FS4 + (2*jp+1)*16 + cg] = make_float4(a0.y, a1.y, a2.y, a3.y);
        }
    }
    __syncthreads();

    // ---- phase 3: out[o][p] = dot(cv2[o], feat[p]), lane-over-d, partition-reduce ----
    {
        int warp = t >> 5, lane = t & 31;
        int g    = warp >> 1;                   // o group 0..3
        int pbase = (warp & 1) * 8;             // 8 points per warp
        const ulonglong2* cv2 = (const ulonglong2*)g_cvP;
        const ulonglong2* sf2 = (const ulonglong2*)s_feat;
        float* s_fin = s_mat3;                  // reuse: [o][p] 64x16

        #pragma unroll 1
        for (int it = 0; it < 4; it++) {
            int obase = g*4 + it*16;
            ull acc[4][8];
            #pragma unroll
            for (int oi = 0; oi < 4; oi++)
                #pragma unroll
                for (int pi = 0; pi < 8; pi++) acc[oi][pi] = 0ull;

            #pragma unroll 1
            for (int s = 0; s < 8; s++) {
                ulonglong2 wv0 = cv2[(obase + 0)*256 + s*32 + lane];
                ulonglong2 wv1 = cv2[(obase + 1)*256 + s*32 + lane];
                ulonglong2 wv2 = cv2[(obase + 2)*256 + s*32 + lane];
                ulonglong2 wv3 = cv2[(obase + 3)*256 + s*32 + lane];
                const ulonglong2* fp = sf2 + pbase*FS4 + s*32 + lane;
                #pragma unroll
                for (int pi = 0; pi < 8; pi++) {
                    ulonglong2 fv = fp[pi*FS4];
                    acc[0][pi] = fma2(wv0.x, fv.x, acc[0][pi]);
                    acc[0][pi] = fma2(wv0.y, fv.y, acc[0][pi]);
                    acc[1][pi] = fma2(wv1.x, fv.x, acc[1][pi]);
                    acc[1][pi] = fma2(wv1.y, fv.y, acc[1][pi]);
                    acc[2][pi] = fma2(wv2.x, fv.x, acc[2][pi]);
                    acc[2][pi] = fma2(wv2.y, fv.y, acc[2][pi]);
                    acc[3][pi] = fma2(wv3.x, fv.x, acc[3][pi]);
                    acc[3][pi] = fma2(wv3.y, fv.y, acc[3][pi]);
                }
            }
            // partition-reduce the 32 (oi,pi) partial sums: 31 shfl, lane l ends
            // with the full sum for output index l (oi = l>>3, pi = l&7)
            float v[32];
            #pragma unroll
            for (int oi = 0; oi < 4; oi++)
                #pragma unroll
                for (int pi = 0; pi < 8; pi++) {
                    float2 h = unpack2(acc[oi][pi]);
                    v[oi*8 + pi] = h.x + h.y;
                }
            float r = preduce32(v, lane);
            s_fin[(obase + (lane >> 3))*16 + pbase + (lane & 7)] = r;
        }
    }
    __syncthreads();

    // coalesced output write: 64 o x 16 p = 1024 floats, 256 threads x float4
    {
        int o = t >> 2, pq = t & 3;
        float4 v = ((const float4*)s_mat3)[o*4 + pq];
        ((float4*)out)[((size_t)(b*64 + o))*2048 + (m0 >> 2) + pq] = v;
    }
}

// ---------------- launch ----------------
extern "C" void kernel_launch(void* const* d_in, const int* in_sizes, int n_in,
                              void* d_out, int out_size) {
    const float* x     = (const float*)d_in[0];
    const float* pos   = (const float*)d_in[1];
    const float* sup   = (const float*)d_in[2];
    const int*   nbr   = (const int*)  d_in[3];
    const float* alpha = (const float*)d_in[4];
    const float* beta  = (const float*)d_in[5];
    const float* nr    = (const float*)d_in[6];
    const float* fc1   = (const float*)d_in[7];
    const float* fc2   = (const float*)d_in[8];
    const float* fc3   = (const float*)d_in[9];
    const float* bn1w  = (const float*)d_in[10];
    const float* bn1b  = (const float*)d_in[11];
    const float* bn2w  = (const float*)d_in[12];
    const float* bn2b  = (const float*)d_in[13];
    const float* cvw   = (const float*)d_in[14];
    float* out = (float*)d_out;

    cudaFuncSetAttribute((const void*)k4, cudaFuncAttributeMaxDynamicSharedMemorySize, K4_SMEM);

    k_xt    <<<dim3(N_/32, C_/32, B_), dim3(32, 8)>>>(x);
    k_pos   <<<dim3(N_/256, B_), 256>>>(pos);
    k_cvp   <<<256, 256>>>(cvw);
    k1      <<<dim3(NBLK1, B_), 256>>>(sup, nbr, alpha, beta, nr);
    k_stats1<<<B_, 512>>>(fc1, bn1w, bn1b);
    k2      <<<dim3(NBLK1, B_), 256>>>(fc1, fc2);
    k_stats2<<<B_, 1024>>>(bn2w, bn2b);
    k4      <<<dim3(M_/PTS_, B_), 256, K4_SMEM>>>(nbr, fc3, out);
}